// round 13
// baseline (speedup 1.0000x reference)
#include <cuda_runtime.h>
#include <cuda_fp16.h>
#include <cstdint>
#include <math.h>

// Problem constants
#define BTOT 32768      // BS*T = 128*256
#define SD   512        // STATE_DIM
#define EMB  32
#define HYP  256

// ---------------- global scratch (no allocations allowed) ----------------
__device__ __half g_Yh [(size_t)BTOT * SD];          // y (single fp16)
__device__ __half g_H1h[(size_t)BTOT * HYP];         // H1 (single fp16)
__device__ __half g_HFh[(size_t)BTOT * HYP];         // HF (single fp16)
__device__ __half g_W1[(size_t)BTOT * 256];          // abs(H1@W1b+b1b)  fp16
__device__ float g_B1[(size_t)BTOT * EMB];           // y@Wb1+bb1
__device__ float g_Hv[(size_t)BTOT * EMB];           // relu(y@Wv1+bv1)
__device__ float g_WF[(size_t)BTOT * EMB];           // abs(HF@Wfb+bfb)

// transposed weights: [n][k] single fp16 (n padded for BN=128 tiles)
#define N0PAD 640
__device__ __half g_WT0[N0PAD * 512];                // [W1a|Wfa|Wb1|Wv1|0]^T
__device__ __half g_WT1[320 * 256];                  // [W1b|Wfb|pad]^T

__device__ __forceinline__ uint32_t smem_u32(const void* p) {
    return (uint32_t)__cvta_generic_to_shared(p);
}

#define LDSM4(r0, r1, r2, r3, addr) \
    asm volatile("ldmatrix.sync.aligned.m8n8.x4.shared.b16 {%0,%1,%2,%3}, [%4];" \
        : "=r"(r0), "=r"(r1), "=r"(r2), "=r"(r3) : "r"(addr))

#define MMA_F16(c, a, b) \
    asm volatile("mma.sync.aligned.m16n8k16.row.col.f32.f16.f16.f32 " \
        "{%0,%1,%2,%3}, {%4,%5,%6,%7}, {%8,%9}, {%0,%1,%2,%3};" \
        : "+f"((c)[0]), "+f"((c)[1]), "+f"((c)[2]), "+f"((c)[3]) \
        : "r"((a)[0]), "r"((a)[1]), "r"((a)[2]), "r"((a)[3]), \
          "r"((b)[0]), "r"((b)[1]))

#define CP16(dst, src) \
    asm volatile("cp.async.cg.shared.global [%0], [%1], 16;" :: "r"(dst), "l"(src))
#define CP_COMMIT() asm volatile("cp.async.commit_group;" ::: "memory")
#define CP_WAIT(n)  asm volatile("cp.async.wait_group %0;" :: "n"(n) : "memory")

__device__ __forceinline__ void h_split(float v, __half& h, __half& l) {
    h = __float2half_rn(v);
    l = __float2half_rn(v - __half2float(h));
}

// =========================================================================
// k1_mma: token embed on tensor cores + fused weight-prep blocks.
// blocks [0, 2048): embed path (states -> g_Yh)
// blocks [2048, 2048+1600): prep path (transpose weights to g_WT0/g_WT1)
// =========================================================================
#define P_A 72
#define P_E 40

#define K1_sAh  0
#define K1_sAl  (K1_sAh + 128 * P_A * 2)      // 18432
#define K1_sBh  (K1_sAl + 128 * P_A * 2)      // 36864 (Wtok^T [32][72])
#define K1_sEh  (K1_sBh + 32 * P_A * 2)       // 41472 (E hi [128][40])
#define K1_sEl  (K1_sEh + 128 * P_E * 2)      // 51712
#define K1_sCh  (K1_sEl + 128 * P_E * 2)      // 61952 (Wyfc^T [64][40])
#define K1_SMEM (K1_sCh + 64 * P_E * 2)       // 67072

#define PREP_BLOCKS ((N0PAD * 512 + 320 * 256 + 255) / 256)   // 1600

__global__ __launch_bounds__(256, 2) void k1_mma(
    const float* __restrict__ states,
    const float* __restrict__ Wt, const float* __restrict__ bt,
    const float* __restrict__ Wy, const float* __restrict__ by,
    const float* __restrict__ W1a, const float* __restrict__ Wfa,
    const float* __restrict__ Wb1, const float* __restrict__ Wv1,
    const float* __restrict__ W1b, const float* __restrict__ Wfb)
{
    // ---------------- prep path ----------------
    if (blockIdx.x >= 2048) {
        int idx = (blockIdx.x - 2048) * 256 + threadIdx.x;
        if (idx < N0PAD * 512) {
            int n = idx >> 9, k = idx & 511;
            float v = 0.f;
            if (n < 256)      v = W1a[k * 256 + n];
            else if (n < 512) v = Wfa[k * 256 + (n - 256)];
            else if (n < 544) v = Wb1[k * 32 + (n - 512)];
            else if (n < 576) v = Wv1[k * 32 + (n - 544)];
            g_WT0[idx] = __float2half_rn(v);
        }
        int idx2 = idx - N0PAD * 512;
        if (idx2 >= 0 && idx2 < 320 * 256) {
            int n = idx2 >> 8, k = idx2 & 255;
            float v = 0.f;
            if (n < 256)      v = W1b[k * 256 + n];
            else if (n < 288) v = Wfb[k * 32 + (n - 256)];
            g_WT1[idx2] = __float2half_rn(v);
        }
        return;
    }

    // ---------------- embed path ----------------
    extern __shared__ __align__(16) char dsm[];
    const uint32_t sb = smem_u32(dsm);
    const int tid  = threadIdx.x;
    const int w    = tid >> 5;
    const int lane = tid & 31;
    const int g    = lane >> 3;
    const int li   = lane & 7;

    {
        const float4* S4 = (const float4*)(states + (size_t)blockIdx.x * 128 * 64);
        __half* Ah = (__half*)(dsm + K1_sAh);
        __half* Al = (__half*)(dsm + K1_sAl);
        #pragma unroll
        for (int i = 0; i < 8; i++) {
            int idx = tid + i * 256;
            int row = idx >> 4;
            int k4  = (idx & 15) * 4;
            float4 v = S4[idx];
            int e = row * P_A + k4;
            __half h0,l0,h1,l1,h2,l2,h3,l3;
            h_split(v.x,h0,l0); h_split(v.y,h1,l1);
            h_split(v.z,h2,l2); h_split(v.w,h3,l3);
            *(__half2*)&Ah[e]   = __halves2half2(h0,h1);
            *(__half2*)&Ah[e+2] = __halves2half2(h2,h3);
            *(__half2*)&Al[e]   = __halves2half2(l0,l1);
            *(__half2*)&Al[e+2] = __halves2half2(l2,l3);
        }
        __half* Bh = (__half*)(dsm + K1_sBh);
        #pragma unroll
        for (int i = 0; i < 8; i++) {
            int idx = tid + i * 256;
            int n = idx & 31, k = idx >> 5;
            Bh[n * P_A + k] = __float2half_rn(Wt[k * 32 + n]);
        }
        __half* Ch = (__half*)(dsm + K1_sCh);
        #pragma unroll
        for (int i = 0; i < 8; i++) {
            int idx = tid + i * 256;
            int n = idx & 63, k = idx >> 6;
            Ch[n * P_E + k] = __float2half_rn(Wy[k * 64 + n]);
        }
    }
    __syncthreads();

    // ---- stage1: E = relu(A @ Wtok + bt) ----
    {
        float acc[4][4];
        #pragma unroll
        for (int i = 0; i < 4; i++)
            #pragma unroll
            for (int q = 0; q < 4; q++) acc[i][q] = 0.f;

        #pragma unroll
        for (int ks = 0; ks < 4; ks++) {
            const int am = w * 16 + (g & 1) * 8 + li;
            const int ak = (g >> 1) * 8 + ks * 16;
            const int bn = (g >> 1) * 8 + li;
            const int bk = (g & 1) * 8 + ks * 16;
            uint32_t ah[4], al[4], bh[4][2];
            LDSM4(ah[0],ah[1],ah[2],ah[3], sb + K1_sAh + (am * P_A + ak) * 2);
            LDSM4(al[0],al[1],al[2],al[3], sb + K1_sAl + (am * P_A + ak) * 2);
            #pragma unroll
            for (int bp = 0; bp < 2; bp++) {
                LDSM4(bh[2*bp][0], bh[2*bp][1], bh[2*bp+1][0], bh[2*bp+1][1],
                      sb + K1_sBh + ((bn + bp * 16) * P_A + bk) * 2);
            }
            #pragma unroll
            for (int ni = 0; ni < 4; ni++) {
                MMA_F16(acc[ni], ah, bh[ni]);
                MMA_F16(acc[ni], al, bh[ni]);
            }
        }
        __half* Eh = (__half*)(dsm + K1_sEh);
        __half* El = (__half*)(dsm + K1_sEl);
        #pragma unroll
        for (int ni = 0; ni < 4; ni++) {
            int n = ni * 8 + 2 * (lane & 3);
            float b0 = bt[n], b1 = bt[n + 1];
            #pragma unroll
            for (int half = 0; half < 2; half++) {
                int m = w * 16 + (lane >> 2) + half * 8;
                float o0 = fmaxf(acc[ni][half*2+0] + b0, 0.f);
                float o1 = fmaxf(acc[ni][half*2+1] + b1, 0.f);
                __half h0,l0,h1,l1;
                h_split(o0,h0,l0); h_split(o1,h1,l1);
                *(__half2*)&Eh[m * P_E + n] = __halves2half2(h0,h1);
                *(__half2*)&El[m * P_E + n] = __halves2half2(l0,l1);
            }
        }
    }
    __syncthreads();

    // ---- stage2: Y = relu(E @ Wyfc + by), N=64 -> single fp16 ----
    {
        float acc[8][4];
        #pragma unroll
        for (int i = 0; i < 8; i++)
            #pragma unroll
            for (int q = 0; q < 4; q++) acc[i][q] = 0.f;

        #pragma unroll
        for (int ks = 0; ks < 2; ks++) {
            const int am = w * 16 + (g & 1) * 8 + li;
            const int ak = (g >> 1) * 8 + ks * 16;
            const int bn = (g >> 1) * 8 + li;
            const int bk = (g & 1) * 8 + ks * 16;
            uint32_t ah[4], al[4], bh[8][2];
            LDSM4(ah[0],ah[1],ah[2],ah[3], sb + K1_sEh + (am * P_E + ak) * 2);
            LDSM4(al[0],al[1],al[2],al[3], sb + K1_sEl + (am * P_E + ak) * 2);
            #pragma unroll
            for (int bp = 0; bp < 4; bp++) {
                LDSM4(bh[2*bp][0], bh[2*bp][1], bh[2*bp+1][0], bh[2*bp+1][1],
                      sb + K1_sCh + ((bn + bp * 16) * P_E + bk) * 2);
            }
            #pragma unroll
            for (int ni = 0; ni < 8; ni++) {
                MMA_F16(acc[ni], ah, bh[ni]);
                MMA_F16(acc[ni], al, bh[ni]);
            }
        }
        #pragma unroll
        for (int ni = 0; ni < 8; ni++) {
            int n = ni * 8 + 2 * (lane & 3);
            float b0 = by[n], b1 = by[n + 1];
            #pragma unroll
            for (int half = 0; half < 2; half++) {
                int m = w * 16 + (lane >> 2) + half * 8;
                size_t R = (size_t)blockIdx.x * 128 + m;
                float o0 = fmaxf(acc[ni][half*2+0] + b0, 0.f);
                float o1 = fmaxf(acc[ni][half*2+1] + b1, 0.f);
                *(__half2*)&g_Yh[R * 64 + n] =
                    __halves2half2(__float2half_rn(o0), __float2half_rn(o1));
            }
        }
    }
}

// =========================================================================
// gemm0: fp16 single-product, BM=128, BN=128, BK=32. 8 warps, warp 64x32.
// C(B,640p) = Y @ WT0 -> H1 | HF | B1 | Hv.  4-stage cp.async ring.
// =========================================================================
#define PITCH 40
#define M0_MAT (128 * PITCH * 2)               // 10240 (A and B both 128 rows)
#define M0_STAGE (2 * M0_MAT)                  // 20480
#define M0_NSTAGE 4
#define M0_DSMEM (M0_NSTAGE * M0_STAGE)        // 81920

__global__ __launch_bounds__(256) void gemm0(
    const float* __restrict__ b1a, const float* __restrict__ bfa,
    const float* __restrict__ bb1, const float* __restrict__ bv1)
{
    extern __shared__ __align__(16) char dsm[];
    const uint32_t sbase = smem_u32(dsm);

    const int tid  = threadIdx.x;
    const int wid  = tid >> 5;
    const int lane = tid & 31;
    const int wm   = wid >> 2;          // 0..1 : m-half (64 rows)
    const int wn   = wid & 3;           // 0..3 : n-quarter (32 cols)
    const int nbase = blockIdx.x * 128;
    const int m0    = blockIdx.y * 128;
    const int NC    = 16;

    const int r0 = tid >> 2, k8 = (tid & 3) * 8;

    auto issue = [&](int c) {
        const uint32_t st = sbase + (c & (M0_NSTAGE - 1)) * M0_STAGE;
        #pragma unroll
        for (int i = 0; i < 2; i++) {
            int row = r0 + i * 64;
            uint32_t d = st + row * (PITCH*2) + k8 * 2;
            CP16(d, g_Yh + (size_t)(m0 + row) * 512 + c * 32 + k8);
            CP16(d + M0_MAT, g_WT0 + (size_t)(nbase + row) * 512 + c * 32 + k8);
        }
        CP_COMMIT();
    };

    float acc[4][4][4];
    #pragma unroll
    for (int i = 0; i < 4; i++)
        #pragma unroll
        for (int j = 0; j < 4; j++)
            #pragma unroll
            for (int q = 0; q < 4; q++) acc[i][j][q] = 0.f;

    issue(0); issue(1); issue(2);

    const int g  = lane >> 3;
    const int li = lane & 7;

    for (int c = 0; c < NC; ++c) {
        {
            int rem = NC - 1 - c;
            if (rem >= 2)      CP_WAIT(2);
            else if (rem == 1) CP_WAIT(1);
            else               CP_WAIT(0);
        }
        __syncthreads();
        if (c + 3 < NC) issue(c + 3);

        const uint32_t st = sbase + (c & (M0_NSTAGE - 1)) * M0_STAGE;
        const uint32_t sA = st;
        const uint32_t sB = st + M0_MAT;

        #pragma unroll
        for (int ks = 0; ks < 2; ks++) {
            const int am = wm * 64 + (g & 1) * 8 + li;
            const int ak = (g >> 1) * 8 + ks * 16;
            const int bn = wn * 32 + (g >> 1) * 8 + li;
            const int bk = (g & 1) * 8 + ks * 16;

            uint32_t ah[4][4], bh[4][2];
            #pragma unroll
            for (int mi = 0; mi < 4; mi++) {
                uint32_t a1 = sA + ((am + mi * 16) * PITCH + ak) * 2;
                LDSM4(ah[mi][0], ah[mi][1], ah[mi][2], ah[mi][3], a1);
            }
            #pragma unroll
            for (int bp = 0; bp < 2; bp++) {
                uint32_t a1 = sB + ((bn + bp * 16) * PITCH + bk) * 2;
                LDSM4(bh[2*bp][0], bh[2*bp][1], bh[2*bp+1][0], bh[2*bp+1][1], a1);
            }
            #pragma unroll
            for (int mi = 0; mi < 4; mi++)
                #pragma unroll
                for (int ni = 0; ni < 4; ni++)
                    MMA_F16(acc[mi][ni], ah[mi], bh[ni]);
        }
    }

    // ---- epilogue ----
    #pragma unroll
    for (int mi = 0; mi < 4; mi++) {
        #pragma unroll
        for (int ni = 0; ni < 4; ni++) {
            int m  = m0 + wm * 64 + mi * 16 + (lane >> 2);
            int ng = nbase + wn * 32 + ni * 8 + 2 * (lane & 3);
            #pragma unroll
            for (int half = 0; half < 2; half++) {
                int mm = m + half * 8;
                float x0 = acc[mi][ni][half * 2 + 0];
                float x1 = acc[mi][ni][half * 2 + 1];
                if (ng < 256) {
                    float2 b = *(const float2*)&b1a[ng];
                    float o0 = fmaxf(x0 + b.x, 0.f), o1 = fmaxf(x1 + b.y, 0.f);
                    *(__half2*)&g_H1h[(size_t)mm * 256 + ng] =
                        __halves2half2(__float2half_rn(o0), __float2half_rn(o1));
                } else if (ng < 512) {
                    int nl = ng - 256;
                    float2 b = *(const float2*)&bfa[nl];
                    float o0 = fmaxf(x0 + b.x, 0.f), o1 = fmaxf(x1 + b.y, 0.f);
                    *(__half2*)&g_HFh[(size_t)mm * 256 + nl] =
                        __halves2half2(__float2half_rn(o0), __float2half_rn(o1));
                } else if (ng < 544) {
                    int nl = ng - 512;
                    float2 b = *(const float2*)&bb1[nl];
                    float2 o = make_float2(x0 + b.x, x1 + b.y);
                    *(float2*)&g_B1[(size_t)mm * 32 + nl] = o;
                } else if (ng < 576) {
                    int nl = ng - 544;
                    float2 b = *(const float2*)&bv1[nl];
                    float2 o = make_float2(fmaxf(x0 + b.x, 0.f), fmaxf(x1 + b.y, 0.f));
                    *(float2*)&g_Hv[(size_t)mm * 32 + nl] = o;
                }
            }
        }
    }
}

// =========================================================================
// gemm1: fp16 single-product, BM=128, BN=64, BK=32, 8 warps (32x32).
// blocks 0-3: W1 = abs(H1@W1b+b1b) (fp16 out); block 4: WF = abs(HF@Wfb+bfb)
// 4-stage cp.async ring.
// =========================================================================
#define A_BYTES (128 * PITCH * 2)     // 10240
#define B_BYTES (64 * PITCH * 2)      // 5120
#define STAGE   (A_BYTES + B_BYTES)           // 15360
#define NSTAGE  4
#define DSMEM   (NSTAGE * STAGE)              // 61440

__global__ __launch_bounds__(256) void gemm1(
    const float* __restrict__ b1b, const float* __restrict__ bfb)
{
    extern __shared__ __align__(16) char dsm[];
    const uint32_t sbase = smem_u32(dsm);

    const int tid  = threadIdx.x;
    const int wid  = tid >> 5;
    const int lane = tid & 31;
    const int wm   = wid >> 1;
    const int wn   = wid & 1;
    const int nbase = blockIdx.x * 64;
    const int m0    = blockIdx.y * 128;
    const int NC    = 8;

    const __half* A_p = (blockIdx.x == 4) ? g_HFh : g_H1h;

    const int ar0 = tid >> 2,  ak0 = (tid & 3) * 8;

    auto issue = [&](int c) {
        const uint32_t st = sbase + (c & (NSTAGE - 1)) * STAGE;
        #pragma unroll
        for (int i = 0; i < 2; i++) {
            int row = ar0 + i * 64;
            uint32_t d = st + row * (PITCH*2) + ak0 * 2;
            CP16(d, A_p + (size_t)(m0 + row) * 256 + c * 32 + ak0);
        }
        {
            int n  = ar0;
            uint32_t d = st + A_BYTES + n * (PITCH*2) + ak0 * 2;
            CP16(d, g_WT1 + (size_t)(nbase + n) * 256 + c * 32 + ak0);
        }
        CP_COMMIT();
    };

    float acc[2][4][4];
    #pragma unroll
    for (int i = 0; i < 2; i++)
        #pragma unroll
        for (int j = 0; j < 4; j++)
            #pragma unroll
            for (int q = 0; q < 4; q++) acc[i][j][q] = 0.f;

    issue(0); issue(1); issue(2);

    const int g  = lane >> 3;
    const int li = lane & 7;

    for (int c = 0; c < NC; ++c) {
        {
            int rem = NC - 1 - c;
            if (rem >= 2)      CP_WAIT(2);
            else if (rem == 1) CP_WAIT(1);
            else               CP_WAIT(0);
        }
        __syncthreads();
        if (c + 3 < NC) issue(c + 3);

        const uint32_t st = sbase + (c & (NSTAGE - 1)) * STAGE;
        const uint32_t sA = st;
        const uint32_t sB = st + A_BYTES;

        #pragma unroll
        for (int ks = 0; ks < 2; ks++) {
            const int am = wm * 32 + (g & 1) * 8 + li;
            const int ak = (g >> 1) * 8 + ks * 16;
            const int bn = wn * 32 + (g >> 1) * 8 + li;
            const int bk = (g & 1) * 8 + ks * 16;

            uint32_t ah[2][4], bh[4][2];
            #pragma unroll
            for (int mi = 0; mi < 2; mi++) {
                uint32_t a1 = sA + ((am + mi * 16) * PITCH + ak) * 2;
                LDSM4(ah[mi][0], ah[mi][1], ah[mi][2], ah[mi][3], a1);
            }
            #pragma unroll
            for (int bp = 0; bp < 2; bp++) {
                uint32_t a1 = sB + ((bn + bp * 16) * PITCH + bk) * 2;
                LDSM4(bh[2*bp][0], bh[2*bp][1], bh[2*bp+1][0], bh[2*bp+1][1], a1);
            }
            #pragma unroll
            for (int mi = 0; mi < 2; mi++)
                #pragma unroll
                for (int ni = 0; ni < 4; ni++)
                    MMA_F16(acc[mi][ni], ah[mi], bh[ni]);
        }
    }

    // ---- epilogue ----
    #pragma unroll
    for (int mi = 0; mi < 2; mi++) {
        #pragma unroll
        for (int ni = 0; ni < 4; ni++) {
            int m  = m0 + wm * 32 + mi * 16 + (lane >> 2);
            int ng = nbase + wn * 32 + ni * 8 + 2 * (lane & 3);
            #pragma unroll
            for (int half = 0; half < 2; half++) {
                int mm = m + half * 8;
                float x0 = acc[mi][ni][half * 2 + 0];
                float x1 = acc[mi][ni][half * 2 + 1];
                if (nbase < 256) {
                    float2 b = *(const float2*)&b1b[ng];
                    float o0 = fabsf(x0 + b.x), o1 = fabsf(x1 + b.y);
                    *(__half2*)&g_W1[(size_t)mm * 256 + ng] =
                        __halves2half2(__float2half_rn(o0), __float2half_rn(o1));
                } else {
                    int nl = ng - 256;
                    if (nl < 32) {
                        float2 b = *(const float2*)&bfb[nl];
                        float2 o = make_float2(fabsf(x0 + b.x), fabsf(x1 + b.y));
                        *(float2*)&g_WF[(size_t)mm * 32 + nl] = o;
                    }
                }
            }
        }
    }
}

// =========================================================================
// K4: final fused epilogue. One warp per row; lane = EMB index e.
// =========================================================================
__device__ __forceinline__ float wred(float v) {
    #pragma unroll
    for (int o = 16; o > 0; o >>= 1) v += __shfl_xor_sync(0xFFFFFFFFu, v, o);
    return v;
}

__global__ __launch_bounds__(256) void k4_final(
    const float* __restrict__ agent_qs,
    const float* __restrict__ Wv2, const float* __restrict__ bv2,
    float* __restrict__ out)
{
    const int w = threadIdx.x >> 5, lane = threadIdx.x & 31;
    const size_t r = (size_t)blockIdx.x * 8 + w;

    const float wv2v = Wv2[lane];

    float q[8];
    #pragma unroll
    for (int a = 0; a < 8; a++) q[a] = agent_qs[r * 8 + a];

    float w1r[8];
    const __half* w1p = g_W1 + r * 256;
    #pragma unroll
    for (int a = 0; a < 8; a++) w1r[a] = __half2float(w1p[a * 32 + lane]);

    float x = g_B1[r * 32 + lane];
    #pragma unroll
    for (int a = 0; a < 8; a++) x += q[a] * w1r[a];
    const float h    = (x > 0.f) ? x : expm1f(x);
    const float delu = (h < 0.f) ? expf(h) : 1.f;

    const float wf = g_WF[r * 32 + lane];
    const float hv = g_Hv[r * 32 + lane];

    const float vsum = wred(hv * wv2v);
    const float qt   = wred(h * wf);
    if (lane == 0) out[r] = qt + vsum + bv2[0];

    const float t = delu * wf;
    float* gout = out + BTOT;
    #pragma unroll
    for (int a = 0; a < 8; a++) {
        float s = wred(w1r[a] * t);
        if (lane == a) gout[r * 8 + a] = s;
    }
}

// =========================================================================
extern "C" void kernel_launch(void* const* d_in, const int* in_sizes, int n_in,
                              void* d_out, int out_size)
{
    (void)in_sizes; (void)n_in; (void)out_size;
    const float* agent_qs = (const float*)d_in[0];
    const float* states = (const float*)d_in[2];   // d_in[1]=hist, d_in[3]=obs unused
    const float* W_tok  = (const float*)d_in[4];
    const float* b_tok  = (const float*)d_in[5];
    const float* W_yfc  = (const float*)d_in[6];
    const float* b_yfc  = (const float*)d_in[7];
    const float* W1a    = (const float*)d_in[8];
    const float* b1a    = (const float*)d_in[9];
    const float* W1b    = (const float*)d_in[10];
    const float* b1b    = (const float*)d_in[11];
    const float* Wfa    = (const float*)d_in[12];
    const float* bfa    = (const float*)d_in[13];
    const float* Wfb    = (const float*)d_in[14];
    const float* bfb    = (const float*)d_in[15];
    const float* Wb1    = (const float*)d_in[16];
    const float* bb1    = (const float*)d_in[17];
    const float* Wv1    = (const float*)d_in[18];
    const float* bv1    = (const float*)d_in[19];
    const float* Wv2    = (const float*)d_in[20];
    const float* bv2    = (const float*)d_in[21];
    float* out = (float*)d_out;

    cudaFuncSetAttribute(k1_mma, cudaFuncAttributeMaxDynamicSharedMemorySize, K1_SMEM);
    cudaFuncSetAttribute(gemm0, cudaFuncAttributeMaxDynamicSharedMemorySize, M0_DSMEM);
    cudaFuncSetAttribute(gemm1, cudaFuncAttributeMaxDynamicSharedMemorySize, DSMEM);

    k1_mma<<<2048 + PREP_BLOCKS, 256, K1_SMEM>>>(states, W_tok, b_tok, W_yfc, b_yfc,
                                                 W1a, Wfa, Wb1, Wv1, W1b, Wfb);
    gemm0<<<dim3(5, BTOT / 128), 256, M0_DSMEM>>>(b1a, bfa, bb1, bv1);
    gemm1<<<dim3(5, BTOT / 128), 256, DSMEM>>>(b1b, bfb);
    k4_final<<<BTOT / 8, 256>>>(agent_qs, Wv2, bv2, out);
}